// round 7
// baseline (speedup 1.0000x reference)
#include <cuda_runtime.h>
#include <cstdint>

// ============================================================
// BASE MoE layer (sm_103 plain-target: mma.sync tf32 + cp.async)
// out[t] = x[t] + sigmoid(score)*( relu(LN_e(x) W1e^T + b1e) W2e^T + b2e )
// R7: single persistent fused GEMM kernel; task list = GEMM1 tiles,
//     GEMM2 split-K tiles (gated on per-mtile counters), combine tasks.
// ============================================================

#define TOKS 1024
#define DDIM 1024
#define FDIM 4096
#define NEXP 8
#define ROWS_PAD 1152
#define MAX_MT 16
#define KSPLIT 4
#define STAGES 3
#define ROWPAD 36                       // 32 floats + 4 pad
#define STAGE_FLOATS (128 * ROWPAD)     // 4608
#define SMEM_GEMM (2 * STAGES * STAGE_FLOATS * 4)   // 110,592 B

// -------------------- device scratch --------------------
__device__ float g_xn[ROWS_PAD * DDIM];            // LN'd, sorted, permuted, tf32-rounded
__device__ float g_H [ROWS_PAD * FDIM];            // FF1 out, permuted, tf32-rounded
__device__ float g_part[KSPLIT * ROWS_PAD * DDIM]; // GEMM2 split-K partials
__device__ float g_mean[TOKS], g_rstd[TOKS], g_alpha[TOKS];
__device__ float g_alpha_s[TOKS];
__device__ int   g_eid[TOKS], g_eid_s[TOKS], g_tok[TOKS];
__device__ int   g_mt_e[MAX_MT], g_mt_r0[MAX_MT], g_mt_r1[MAX_MT];
__device__ int   g_num_mt;
__device__ int   g_cnt1[MAX_MT];   // GEMM1 tiles finished per m-tile
__device__ int   g_cnt2[MAX_MT];   // GEMM2 tiles finished per m-tile

// -------------------- PTX helpers --------------------
__device__ __forceinline__ void cp16(uint32_t dst, const void* src) {
    asm volatile("cp.async.cg.shared.global [%0], [%1], 16;" :: "r"(dst), "l"(src));
}
__device__ __forceinline__ void cp_commit() {
    asm volatile("cp.async.commit_group;" ::: "memory");
}
__device__ __forceinline__ void cp_wait1() {
    asm volatile("cp.async.wait_group 1;" ::: "memory");
}
__device__ __forceinline__ uint32_t f2tf32(float v) {
    uint32_t r;
    asm("cvt.rna.tf32.f32 %0, %1;" : "=r"(r) : "f"(v));
    return r;
}
__device__ __forceinline__ float roundtf(float v) { return __uint_as_float(f2tf32(v)); }
__device__ __forceinline__ void mma_tf32(float* c, const uint32_t* a, const uint32_t* b) {
    asm volatile(
        "mma.sync.aligned.m16n8k8.row.col.f32.tf32.tf32.f32 "
        "{%0,%1,%2,%3}, {%4,%5,%6,%7}, {%8,%9}, {%0,%1,%2,%3};"
        : "+f"(c[0]), "+f"(c[1]), "+f"(c[2]), "+f"(c[3])
        : "r"(a[0]), "r"(a[1]), "r"(a[2]), "r"(a[3]), "r"(b[0]), "r"(b[1]));
}
// permuted position of logical k within its 8-col group: [0,4,1,5,2,6,3,7]
__device__ __forceinline__ int pidx(int k) { return ((k & 3) << 1) | ((k & 4) >> 2); }

// -------------------- routing --------------------
__global__ void route_kernel(const float* __restrict__ x, const float* __restrict__ cent) {
    int t = blockIdx.x, tid = threadIdx.x;
    const float4* xr = (const float4*)(x + (size_t)t * DDIM);
    float sum = 0.f, sq = 0.f, acc[NEXP];
#pragma unroll
    for (int e = 0; e < NEXP; e++) acc[e] = 0.f;
    for (int i = tid; i < DDIM / 4; i += 128) {
        float4 xv = xr[i];
#pragma unroll
        for (int e = 0; e < NEXP; e++) {
            float4 cv = ((const float4*)cent)[e * (DDIM / 4) + i];
            acc[e] += xv.x * cv.x + xv.y * cv.y + xv.z * cv.z + xv.w * cv.w;
        }
        sum += xv.x + xv.y + xv.z + xv.w;
        sq  += xv.x * xv.x + xv.y * xv.y + xv.z * xv.z + xv.w * xv.w;
    }
#pragma unroll
    for (int o = 16; o > 0; o >>= 1) {
        sum += __shfl_xor_sync(0xffffffffu, sum, o);
        sq  += __shfl_xor_sync(0xffffffffu, sq,  o);
#pragma unroll
        for (int e = 0; e < NEXP; e++) acc[e] += __shfl_xor_sync(0xffffffffu, acc[e], o);
    }
    __shared__ float sh[4][NEXP + 2];
    int wid = tid >> 5, lid = tid & 31;
    if (lid == 0) {
        sh[wid][0] = sum; sh[wid][1] = sq;
#pragma unroll
        for (int e = 0; e < NEXP; e++) sh[wid][2 + e] = acc[e];
    }
    __syncthreads();
    if (tid == 0) {
        float s = 0.f, q = 0.f, a[NEXP];
#pragma unroll
        for (int e = 0; e < NEXP; e++) a[e] = 0.f;
        for (int w = 0; w < 4; w++) {
            s += sh[w][0]; q += sh[w][1];
#pragma unroll
            for (int e = 0; e < NEXP; e++) a[e] += sh[w][2 + e];
        }
        float mu  = s * (1.f / DDIM);
        float var = q * (1.f / DDIM) - mu * mu;
        g_mean[t] = mu;
        g_rstd[t] = rsqrtf(var + 1e-5f);
        int be = 0; float bs = a[0];
#pragma unroll
        for (int e = 1; e < NEXP; e++) if (a[e] > bs) { bs = a[e]; be = e; }
        g_eid[t]   = be;
        g_alpha[t] = 1.f / (1.f + expf(-bs));
    }
}

// -------------------- counting sort + m-tile descriptors + counter reset ----
__global__ void sort_kernel() {
    __shared__ int cnt[NEXP], ctr[NEXP];
    int t = threadIdx.x;
    if (t < NEXP) cnt[t] = 0;
    if (t < MAX_MT) { g_cnt1[t] = 0; g_cnt2[t] = 0; }
    __syncthreads();
    int e = g_eid[t];
    atomicAdd(&cnt[e], 1);
    __syncthreads();
    if (t == 0) {
        int o = 0, nm = 0;
        for (int k = 0; k < NEXP; k++) {
            ctr[k] = o;
            int c = cnt[k];
            for (int i = 0; i < c; i += 128) {
                g_mt_e[nm]  = k;
                g_mt_r0[nm] = o + i;
                g_mt_r1[nm] = o + ((i + 128 < c) ? (i + 128) : c);
                nm++;
            }
            o += c;
        }
        g_num_mt = nm;
    }
    __syncthreads();
    int pos = atomicAdd(&ctr[e], 1);
    g_tok[pos] = t;
    g_eid_s[pos] = e;
    g_alpha_s[pos] = g_alpha[t];
}

// -------------------- LN scatter (permuted + tf32-rounded) --------------------
__global__ void ln_kernel(const float* __restrict__ x, const float* __restrict__ gamma,
                          const float* __restrict__ beta) {
    int p = blockIdx.x, tid = threadIdx.x;
    int t = g_tok[p], e = g_eid_s[p];
    float mu = g_mean[t], rs = g_rstd[t];
    const float4* xr = (const float4*)(x + (size_t)t * DDIM);
    const float4* gr = (const float4*)(gamma + (size_t)e * DDIM);
    const float4* br = (const float4*)(beta + (size_t)e * DDIM);
    float* o = g_xn + (size_t)p * DDIM;
    for (int i = tid; i < DDIM / 4; i += 128) {
        float4 xv = xr[i], gv = gr[i], bv = br[i];
        int c0 = 4 * i;
        int g = c0 & ~7;
        int off = (c0 & 4) ? 1 : 0;
        o[g + off + 0] = roundtf((xv.x - mu) * rs * gv.x + bv.x);
        o[g + off + 2] = roundtf((xv.y - mu) * rs * gv.y + bv.y);
        o[g + off + 4] = roundtf((xv.z - mu) * rs * gv.z + bv.z);
        o[g + off + 6] = roundtf((xv.w - mu) * rs * gv.w + bv.w);
    }
}

// -------------------- one GEMM tile (device function) --------------------
// MODE 1: g_H tile = relu(A W^T + b), permuted+rounded store, bump g_cnt1[mt]
// MODE 2: g_part[bz] tile = partial(A W^T), bump g_cnt2[mt]
template<int KCHUNK, int KFULL, int NDIM, int MODE>
__device__ __forceinline__ void gemm_tile(
    const float* __restrict__ A, const float* __restrict__ W,
    const float* __restrict__ bias, float* __restrict__ outp,
    int mt, int nt, int bz, float* sh)
{
    int e = g_mt_e[mt], row0 = g_mt_r0[mt], row1 = g_mt_r1[mt];
    int n0 = nt * 128;
    int k0 = bz * KCHUNK;

    float* shB = sh + STAGES * STAGE_FLOATS;
    uint32_t sA, sB;
    {
        uint32_t base;
        asm("{ .reg .u64 t; cvta.to.shared.u64 t, %1; cvt.u32.u64 %0, t; }"
            : "=r"(base) : "l"(sh));
        sA = base;
        sB = base + STAGES * STAGE_FLOATS * 4;
    }

    int tid = threadIdx.x;
    int lane = tid & 31, wid = tid >> 5;
    int wm = wid >> 2, wn = wid & 3;          // 2 x 4 warp grid
    int lg = lane >> 2, lt = lane & 3;

    const int KT = KCHUNK / 32;

    float acc[4][4][4];
#pragma unroll
    for (int a = 0; a < 4; a++)
#pragma unroll
        for (int b = 0; b < 4; b++)
#pragma unroll
            for (int c = 0; c < 4; c++) acc[a][b][c] = 0.f;

    const float* Abase = A + (size_t)row0 * KFULL + k0;
    const float* Wbase = W + ((size_t)e * NDIM + n0) * KFULL + k0;

    auto load_stage = [&](int it, int s) {
        if (it < KT) {
            int kk0 = it * 32;
            uint32_t dA = sA + s * (STAGE_FLOATS * 4);
            uint32_t dB = sB + s * (STAGE_FLOATS * 4);
#pragma unroll
            for (int i = 0; i < 4; i++) {
                int chunk = tid + i * 256;
                int r = chunk >> 3, c = chunk & 7;
                cp16(dA + r * (ROWPAD * 4) + c * 16, Abase + (size_t)r * KFULL + kk0 + c * 4);
            }
#pragma unroll
            for (int i = 0; i < 4; i++) {
                int chunk = tid + i * 256;
                int r = chunk >> 3, c = chunk & 7;
                cp16(dB + r * (ROWPAD * 4) + c * 16, Wbase + (size_t)r * KFULL + kk0 + c * 4);
            }
        }
        cp_commit();
    };

    __syncthreads();   // previous task fully done with smem
    load_stage(0, 0);
    load_stage(1, 1);

    for (int it = 0; it < KT; it++) {
        cp_wait1();
        __syncthreads();
        load_stage(it + 2, (it + 2) % STAGES);

        int s = it % STAGES;
        const float* As = sh  + s * STAGE_FLOATS;
        const float* Bs = shB + s * STAGE_FLOATS;

#pragma unroll
        for (int kk = 0; kk < 4; kk++) {
            uint32_t afr[4][4], bfr[4][2];
#pragma unroll
            for (int m = 0; m < 4; m++) {
                const float* ap = As + (wm * 64 + m * 16 + lg) * ROWPAD + kk * 8 + 2 * lt;
                uint2 lo = *(const uint2*)ap;                 // rows lg
                uint2 hi = *(const uint2*)(ap + 8 * ROWPAD);  // rows lg+8
                afr[m][0] = lo.x; afr[m][2] = lo.y;
                afr[m][1] = hi.x; afr[m][3] = hi.y;
            }
#pragma unroll
            for (int n = 0; n < 4; n++) {
                const float* bp = Bs + (wn * 32 + n * 8 + lg) * ROWPAD + kk * 8 + lt;
                bfr[n][0] = f2tf32(bp[0]);
                bfr[n][1] = f2tf32(bp[4]);
            }
#pragma unroll
            for (int m = 0; m < 4; m++)
#pragma unroll
                for (int n = 0; n < 4; n++)
                    mma_tf32(acc[m][n], afr[m], bfr[n]);
        }
    }

    // -------------------- epilogue --------------------
#pragma unroll
    for (int m = 0; m < 4; m++) {
#pragma unroll
        for (int half = 0; half < 2; half++) {
            int r = wm * 64 + m * 16 + half * 8 + lg;
            int p = row0 + r;
            if (p >= row1) continue;
            if (MODE == 1) {
                float* dst = outp + (size_t)p * NDIM + n0;
                const float* bs = bias + (size_t)e * NDIM + n0;
#pragma unroll
                for (int n = 0; n < 4; n++) {
                    int col8 = wn * 32 + n * 8;
                    int j0 = 2 * lt, j1 = 2 * lt + 1;
                    float v0 = fmaxf(acc[m][n][half * 2 + 0] + bs[col8 + j0], 0.f);
                    float v1 = fmaxf(acc[m][n][half * 2 + 1] + bs[col8 + j1], 0.f);
                    dst[col8 + pidx(j0)] = roundtf(v0);
                    dst[col8 + pidx(j1)] = roundtf(v1);
                }
            } else {
                float* dst = outp + ((size_t)bz * ROWS_PAD + p) * NDIM + n0;
#pragma unroll
                for (int n = 0; n < 4; n++) {
                    int col = wn * 32 + n * 8 + 2 * lt;
                    float2 o;
                    o.x = acc[m][n][half * 2 + 0];
                    o.y = acc[m][n][half * 2 + 1];
                    *(float2*)(dst + col) = o;
                }
            }
        }
    }
    __threadfence();
    __syncthreads();
    if (tid == 0) {
        if (MODE == 1) atomicAdd(&g_cnt1[mt], 1);
        else           atomicAdd(&g_cnt2[mt], 1);
    }
}

// -------------------- combine task --------------------
__device__ __forceinline__ void combine_tile(int mt, const float* __restrict__ x,
                                             const float* __restrict__ b2,
                                             float* __restrict__ out) {
    int row0 = g_mt_r0[mt], row1 = g_mt_r1[mt];
    int nrows = row1 - row0;
    int tid = threadIdx.x;
    for (int idx = tid; idx < nrows * (DDIM / 4); idx += 256) {
        int p = row0 + (idx >> 8);
        int i = idx & 255;
        int t = g_tok[p], e = g_eid_s[p];
        float al = g_alpha_s[p];
        float4 s = ((const float4*)(g_part + (size_t)p * DDIM))[i];
#pragma unroll
        for (int z = 1; z < KSPLIT; z++) {
            float4 v = ((const float4*)(g_part + ((size_t)z * ROWS_PAD + p) * DDIM))[i];
            s.x += v.x; s.y += v.y; s.z += v.z; s.w += v.w;
        }
        float4 xv = ((const float4*)(x + (size_t)t * DDIM))[i];
        float4 bv = ((const float4*)(b2 + (size_t)e * DDIM))[i];
        float4 o;
        o.x = xv.x + al * (s.x + bv.x);
        o.y = xv.y + al * (s.y + bv.y);
        o.z = xv.z + al * (s.z + bv.z);
        o.w = xv.w + al * (s.w + bv.w);
        ((float4*)(out + (size_t)t * DDIM))[i] = o;
    }
}

// -------------------- spin gate --------------------
__device__ __forceinline__ void spin_until(int* p, int tgt) {
    if (threadIdx.x == 0) {
        while (atomicAdd(p, 0) < tgt) __nanosleep(200);
        __threadfence();
    }
    __syncthreads();
}

// -------------------- persistent fused GEMM kernel --------------------
__global__ void __launch_bounds__(256, 2) moe_persistent(
    const float* __restrict__ x,
    const float* __restrict__ W1, const float* __restrict__ b1,
    const float* __restrict__ W2, const float* __restrict__ b2,
    float* __restrict__ out)
{
    extern __shared__ float sh[];
    int nm = g_num_mt;
    int NG1 = 32 * nm;          // GEMM1: mt*32 + nt(0..31)
    int NG2 = 32 * nm;          // GEMM2: mt*32 + z*8 + nt(0..7), KSPLIT=4
    int total = NG1 + NG2 + nm;

    for (int task = blockIdx.x; task < total; task += gridDim.x) {
        if (task < NG1) {
            int mt = task >> 5, nt = task & 31;
            gemm_tile<DDIM, DDIM, FDIM, 1>(g_xn, W1, b1, g_H, mt, nt, 0, sh);
        } else if (task < NG1 + NG2) {
            int t2 = task - NG1;
            int mt = t2 >> 5, s = t2 & 31;
            int z = s >> 3, nt = s & 7;
            spin_until(&g_cnt1[mt], 32);
            gemm_tile<FDIM / KSPLIT, FDIM, DDIM, 2>(g_H, W2, nullptr, g_part, mt, nt, z, sh);
        } else {
            int mt = task - NG1 - NG2;
            spin_until(&g_cnt2[mt], 32);
            combine_tile(mt, x, b2, out);
        }
    }
}

// -------------------- host --------------------
extern "C" void kernel_launch(void* const* d_in, const int* in_sizes, int n_in,
                              void* d_out, int out_size) {
    const float* x     = (const float*)d_in[0];
    const float* cent  = (const float*)d_in[1];
    const float* gamma = (const float*)d_in[2];
    const float* beta  = (const float*)d_in[3];
    const float* W1    = (const float*)d_in[4];
    const float* b1    = (const float*)d_in[5];
    const float* W2    = (const float*)d_in[6];
    const float* b2    = (const float*)d_in[7];
    float* out = (float*)d_out;

    cudaFuncSetAttribute((const void*)moe_persistent,
                         cudaFuncAttributeMaxDynamicSharedMemorySize, SMEM_GEMM);

    int nsm = 0, bpm = 0;
    cudaDeviceGetAttribute(&nsm, cudaDevAttrMultiProcessorCount, 0);
    cudaOccupancyMaxActiveBlocksPerMultiprocessor(&bpm, moe_persistent, 256, SMEM_GEMM);
    if (bpm < 1) bpm = 1;
    if (nsm < 1) nsm = 148;
    int grid = bpm * nsm;

    route_kernel<<<TOKS, 128>>>(x, cent);
    sort_kernel<<<1, TOKS>>>();
    ln_kernel<<<TOKS, 128>>>(x, gamma, beta);
    moe_persistent<<<grid, 256, SMEM_GEMM>>>(x, W1, b1, W2, b2, out);
}

// round 8
// speedup vs baseline: 1.2655x; 1.2655x over previous
#include <cuda_runtime.h>
#include <cstdint>

// ============================================================
// BASE MoE layer (sm_103 plain-target: mma.sync tf32 + cp.async)
// out[t] = x[t] + sigmoid(score)*( relu(LN_e(x) W1e^T + b1e) W2e^T + b2e )
// R8: 64x64 warp tiles (128 acc regs, 32 indep MMA chains), 128-thread
//     CTAs, 2x2 warp grid, same 128x128 CTA tile + 3-stage pipeline.
// ============================================================

#define TOKS 1024
#define DDIM 1024
#define FDIM 4096
#define NEXP 8
#define ROWS_PAD 1152
#define MAX_MT 16
#define KSPLIT 4
#define STAGES 3
#define ROWPAD 36                       // 32 floats + 4 pad
#define STAGE_FLOATS (128 * ROWPAD)     // 4608
#define SMEM_GEMM (2 * STAGES * STAGE_FLOATS * 4)   // 110,592 B
#define CTA_THREADS 128

// -------------------- device scratch --------------------
__device__ float g_xn[ROWS_PAD * DDIM];            // LN'd, sorted, permuted, tf32-rounded
__device__ float g_H [ROWS_PAD * FDIM];            // FF1 out, permuted, tf32-rounded
__device__ float g_part[KSPLIT * ROWS_PAD * DDIM]; // GEMM2 split-K partials
__device__ float g_mean[TOKS], g_rstd[TOKS], g_alpha[TOKS];
__device__ float g_alpha_s[TOKS];
__device__ int   g_eid[TOKS], g_eid_s[TOKS], g_tok[TOKS];
__device__ int   g_mt_e[MAX_MT], g_mt_r0[MAX_MT], g_mt_r1[MAX_MT];
__device__ int   g_num_mt;

// -------------------- PTX helpers --------------------
__device__ __forceinline__ void cp16(uint32_t dst, const void* src) {
    asm volatile("cp.async.cg.shared.global [%0], [%1], 16;" :: "r"(dst), "l"(src));
}
__device__ __forceinline__ void cp_commit() {
    asm volatile("cp.async.commit_group;" ::: "memory");
}
__device__ __forceinline__ void cp_wait1() {
    asm volatile("cp.async.wait_group 1;" ::: "memory");
}
__device__ __forceinline__ uint32_t f2tf32(float v) {
    uint32_t r;
    asm("cvt.rna.tf32.f32 %0, %1;" : "=r"(r) : "f"(v));
    return r;
}
__device__ __forceinline__ float roundtf(float v) { return __uint_as_float(f2tf32(v)); }
__device__ __forceinline__ void mma_tf32(float* c, const uint32_t* a, const uint32_t* b) {
    asm volatile(
        "mma.sync.aligned.m16n8k8.row.col.f32.tf32.tf32.f32 "
        "{%0,%1,%2,%3}, {%4,%5,%6,%7}, {%8,%9}, {%0,%1,%2,%3};"
        : "+f"(c[0]), "+f"(c[1]), "+f"(c[2]), "+f"(c[3])
        : "r"(a[0]), "r"(a[1]), "r"(a[2]), "r"(a[3]), "r"(b[0]), "r"(b[1]));
}
// permuted position of logical k within its 8-col group: [0,4,1,5,2,6,3,7]
__device__ __forceinline__ int pidx(int k) { return ((k & 3) << 1) | ((k & 4) >> 2); }

// -------------------- routing --------------------
__global__ void route_kernel(const float* __restrict__ x, const float* __restrict__ cent) {
    int t = blockIdx.x, tid = threadIdx.x;
    const float4* xr = (const float4*)(x + (size_t)t * DDIM);
    float sum = 0.f, sq = 0.f, acc[NEXP];
#pragma unroll
    for (int e = 0; e < NEXP; e++) acc[e] = 0.f;
    for (int i = tid; i < DDIM / 4; i += 128) {
        float4 xv = xr[i];
#pragma unroll
        for (int e = 0; e < NEXP; e++) {
            float4 cv = ((const float4*)cent)[e * (DDIM / 4) + i];
            acc[e] += xv.x * cv.x + xv.y * cv.y + xv.z * cv.z + xv.w * cv.w;
        }
        sum += xv.x + xv.y + xv.z + xv.w;
        sq  += xv.x * xv.x + xv.y * xv.y + xv.z * xv.z + xv.w * xv.w;
    }
#pragma unroll
    for (int o = 16; o > 0; o >>= 1) {
        sum += __shfl_xor_sync(0xffffffffu, sum, o);
        sq  += __shfl_xor_sync(0xffffffffu, sq,  o);
#pragma unroll
        for (int e = 0; e < NEXP; e++) acc[e] += __shfl_xor_sync(0xffffffffu, acc[e], o);
    }
    __shared__ float sh[4][NEXP + 2];
    int wid = tid >> 5, lid = tid & 31;
    if (lid == 0) {
        sh[wid][0] = sum; sh[wid][1] = sq;
#pragma unroll
        for (int e = 0; e < NEXP; e++) sh[wid][2 + e] = acc[e];
    }
    __syncthreads();
    if (tid == 0) {
        float s = 0.f, q = 0.f, a[NEXP];
#pragma unroll
        for (int e = 0; e < NEXP; e++) a[e] = 0.f;
        for (int w = 0; w < 4; w++) {
            s += sh[w][0]; q += sh[w][1];
#pragma unroll
            for (int e = 0; e < NEXP; e++) a[e] += sh[w][2 + e];
        }
        float mu  = s * (1.f / DDIM);
        float var = q * (1.f / DDIM) - mu * mu;
        g_mean[t] = mu;
        g_rstd[t] = rsqrtf(var + 1e-5f);
        int be = 0; float bs = a[0];
#pragma unroll
        for (int e = 1; e < NEXP; e++) if (a[e] > bs) { bs = a[e]; be = e; }
        g_eid[t]   = be;
        g_alpha[t] = 1.f / (1.f + expf(-bs));
    }
}

// -------------------- counting sort + m-tile descriptors --------------------
__global__ void sort_kernel() {
    __shared__ int cnt[NEXP], ctr[NEXP];
    int t = threadIdx.x;
    if (t < NEXP) cnt[t] = 0;
    __syncthreads();
    int e = g_eid[t];
    atomicAdd(&cnt[e], 1);
    __syncthreads();
    if (t == 0) {
        int o = 0, nm = 0;
        for (int k = 0; k < NEXP; k++) {
            ctr[k] = o;
            int c = cnt[k];
            for (int i = 0; i < c; i += 128) {
                g_mt_e[nm]  = k;
                g_mt_r0[nm] = o + i;
                g_mt_r1[nm] = o + ((i + 128 < c) ? (i + 128) : c);
                nm++;
            }
            o += c;
        }
        g_num_mt = nm;
    }
    __syncthreads();
    int pos = atomicAdd(&ctr[e], 1);
    g_tok[pos] = t;
    g_eid_s[pos] = e;
    g_alpha_s[pos] = g_alpha[t];
}

// -------------------- LN scatter (permuted + tf32-rounded) --------------------
__global__ void ln_kernel(const float* __restrict__ x, const float* __restrict__ gamma,
                          const float* __restrict__ beta) {
    int p = blockIdx.x, tid = threadIdx.x;
    int t = g_tok[p], e = g_eid_s[p];
    float mu = g_mean[t], rs = g_rstd[t];
    const float4* xr = (const float4*)(x + (size_t)t * DDIM);
    const float4* gr = (const float4*)(gamma + (size_t)e * DDIM);
    const float4* br = (const float4*)(beta + (size_t)e * DDIM);
    float* o = g_xn + (size_t)p * DDIM;
    for (int i = tid; i < DDIM / 4; i += 128) {
        float4 xv = xr[i], gv = gr[i], bv = br[i];
        int c0 = 4 * i;
        int g = c0 & ~7;
        int off = (c0 & 4) ? 1 : 0;
        o[g + off + 0] = roundtf((xv.x - mu) * rs * gv.x + bv.x);
        o[g + off + 2] = roundtf((xv.y - mu) * rs * gv.y + bv.y);
        o[g + off + 4] = roundtf((xv.z - mu) * rs * gv.z + bv.z);
        o[g + off + 6] = roundtf((xv.w - mu) * rs * gv.w + bv.w);
    }
}

// -------------------- grouped GEMM (64x64 warp tiles, 128 threads) --------
// A is permuted+prerounded (g_xn / g_H); W raw row-major [E][N][K].
// MODE 1: g_H = relu(A W^T + b) (permuted+rounded store)
// MODE 2: g_part[z] = partial(A W^T) over K chunk z
template<int KCHUNK, int KFULL, int NDIM, int MODE>
__global__ void __launch_bounds__(CTA_THREADS, 2) gemm_mma(
    const float* __restrict__ A, const float* __restrict__ W,
    const float* __restrict__ bias, float* __restrict__ outp)
{
    int mt = blockIdx.y;
    if (mt >= g_num_mt) return;
    int e = g_mt_e[mt], row0 = g_mt_r0[mt], row1 = g_mt_r1[mt];
    int n0 = blockIdx.x * 128;
    int bz = blockIdx.z;
    int k0 = bz * KCHUNK;

    extern __shared__ float sh[];
    float* shB = sh + STAGES * STAGE_FLOATS;
    uint32_t sA, sB;
    {
        uint32_t base;
        asm("{ .reg .u64 t; cvta.to.shared.u64 t, %1; cvt.u32.u64 %0, t; }"
            : "=r"(base) : "l"(sh));
        sA = base;
        sB = base + STAGES * STAGE_FLOATS * 4;
    }

    int tid = threadIdx.x;
    int lane = tid & 31, wid = tid >> 5;      // 4 warps
    int wm = wid >> 1, wn = wid & 1;          // 2 x 2 warp grid, 64x64 tiles
    int lg = lane >> 2, lt = lane & 3;

    const int KT = KCHUNK / 32;

    float acc[4][8][4];                        // 128 registers
#pragma unroll
    for (int a = 0; a < 4; a++)
#pragma unroll
        for (int b = 0; b < 8; b++)
#pragma unroll
            for (int c = 0; c < 4; c++) acc[a][b][c] = 0.f;

    const float* Abase = A + (size_t)row0 * KFULL + k0;
    const float* Wbase = W + ((size_t)e * NDIM + n0) * KFULL + k0;

    auto load_stage = [&](int it, int s) {
        if (it < KT) {
            int kk0 = it * 32;
            uint32_t dA = sA + s * (STAGE_FLOATS * 4);
            uint32_t dB = sB + s * (STAGE_FLOATS * 4);
#pragma unroll
            for (int i = 0; i < 8; i++) {
                int chunk = tid + i * CTA_THREADS;
                int r = chunk >> 3, c = chunk & 7;
                cp16(dA + r * (ROWPAD * 4) + c * 16, Abase + (size_t)r * KFULL + kk0 + c * 4);
            }
#pragma unroll
            for (int i = 0; i < 8; i++) {
                int chunk = tid + i * CTA_THREADS;
                int r = chunk >> 3, c = chunk & 7;
                cp16(dB + r * (ROWPAD * 4) + c * 16, Wbase + (size_t)r * KFULL + kk0 + c * 4);
            }
        }
        cp_commit();
    };

    load_stage(0, 0);
    load_stage(1, 1);

    for (int it = 0; it < KT; it++) {
        cp_wait1();
        __syncthreads();
        load_stage(it + 2, (it + 2) % STAGES);   // refills slot (it-1)%3: safe post-sync

        int s = it % STAGES;
        const float* As = sh  + s * STAGE_FLOATS;
        const float* Bs = shB + s * STAGE_FLOATS;

#pragma unroll
        for (int kk = 0; kk < 4; kk++) {
            uint32_t afr[4][4], bfr[8][2];
#pragma unroll
            for (int m = 0; m < 4; m++) {
                // permuted layout: float2 at 2*lt = logical (k=lt, k=lt+4)
                const float* ap = As + (wm * 64 + m * 16 + lg) * ROWPAD + kk * 8 + 2 * lt;
                uint2 lo = *(const uint2*)ap;                 // rows lg
                uint2 hi = *(const uint2*)(ap + 8 * ROWPAD);  // rows lg+8
                afr[m][0] = lo.x; afr[m][2] = lo.y;
                afr[m][1] = hi.x; afr[m][3] = hi.y;
            }
#pragma unroll
            for (int n = 0; n < 8; n++) {
                const float* bp = Bs + (wn * 64 + n * 8 + lg) * ROWPAD + kk * 8 + lt;
                bfr[n][0] = f2tf32(bp[0]);
                bfr[n][1] = f2tf32(bp[4]);
            }
#pragma unroll
            for (int m = 0; m < 4; m++)
#pragma unroll
                for (int n = 0; n < 8; n++)
                    mma_tf32(acc[m][n], afr[m], bfr[n]);
        }
    }

    // -------------------- epilogue --------------------
#pragma unroll
    for (int m = 0; m < 4; m++) {
#pragma unroll
        for (int half = 0; half < 2; half++) {
            int r = wm * 64 + m * 16 + half * 8 + lg;
            int p = row0 + r;
            if (p >= row1) continue;
            if (MODE == 1) {
                // relu + bias, tf32-round, permuted store into g_H
                float* dst = outp + (size_t)p * NDIM + n0;
                const float* bs = bias + (size_t)e * NDIM + n0;
#pragma unroll
                for (int n = 0; n < 8; n++) {
                    int col8 = wn * 64 + n * 8;
                    int j0 = 2 * lt, j1 = 2 * lt + 1;
                    float v0 = fmaxf(acc[m][n][half * 2 + 0] + bs[col8 + j0], 0.f);
                    float v1 = fmaxf(acc[m][n][half * 2 + 1] + bs[col8 + j1], 0.f);
                    dst[col8 + pidx(j0)] = roundtf(v0);
                    dst[col8 + pidx(j1)] = roundtf(v1);
                }
            } else {
                // raw partial store into this K-chunk's slab
                float* dst = outp + ((size_t)bz * ROWS_PAD + p) * NDIM + n0;
#pragma unroll
                for (int n = 0; n < 8; n++) {
                    int col = wn * 64 + n * 8 + 2 * lt;
                    float2 o;
                    o.x = acc[m][n][half * 2 + 0];
                    o.y = acc[m][n][half * 2 + 1];
                    *(float2*)(dst + col) = o;
                }
            }
        }
    }
}

// -------------------- split-K combine + gated residual --------------------
__global__ void combine_kernel(const float* __restrict__ x, const float* __restrict__ b2,
                               float* __restrict__ out) {
    int p = blockIdx.x, tid = threadIdx.x;
    int t = g_tok[p], e = g_eid_s[p];
    float al = g_alpha_s[p];
    const float4* xr = (const float4*)(x + (size_t)t * DDIM);
    const float4* bs = (const float4*)(b2 + (size_t)e * DDIM);
    float4* dst = (float4*)(out + (size_t)t * DDIM);
    for (int i = tid; i < DDIM / 4; i += 128) {
        float4 s = ((const float4*)(g_part + (size_t)p * DDIM))[i];
#pragma unroll
        for (int z = 1; z < KSPLIT; z++) {
            float4 v = ((const float4*)(g_part + ((size_t)z * ROWS_PAD + p) * DDIM))[i];
            s.x += v.x; s.y += v.y; s.z += v.z; s.w += v.w;
        }
        float4 xv = xr[i], bv = bs[i], o;
        o.x = xv.x + al * (s.x + bv.x);
        o.y = xv.y + al * (s.y + bv.y);
        o.z = xv.z + al * (s.z + bv.z);
        o.w = xv.w + al * (s.w + bv.w);
        dst[i] = o;
    }
}

// -------------------- host --------------------
extern "C" void kernel_launch(void* const* d_in, const int* in_sizes, int n_in,
                              void* d_out, int out_size) {
    const float* x     = (const float*)d_in[0];
    const float* cent  = (const float*)d_in[1];
    const float* gamma = (const float*)d_in[2];
    const float* beta  = (const float*)d_in[3];
    const float* W1    = (const float*)d_in[4];
    const float* b1    = (const float*)d_in[5];
    const float* W2    = (const float*)d_in[6];
    const float* b2    = (const float*)d_in[7];
    float* out = (float*)d_out;

    void* pxn = nullptr; void* pH = nullptr; void* ppart = nullptr;
    cudaGetSymbolAddress(&pxn, g_xn);
    cudaGetSymbolAddress(&pH,  g_H);
    cudaGetSymbolAddress(&ppart, g_part);

    cudaFuncSetAttribute((const void*)gemm_mma<DDIM, DDIM, FDIM, 1>,
                         cudaFuncAttributeMaxDynamicSharedMemorySize, SMEM_GEMM);
    cudaFuncSetAttribute((const void*)gemm_mma<FDIM / KSPLIT, FDIM, DDIM, 2>,
                         cudaFuncAttributeMaxDynamicSharedMemorySize, SMEM_GEMM);

    route_kernel<<<TOKS, 128>>>(x, cent);
    sort_kernel<<<1, TOKS>>>();
    ln_kernel<<<TOKS, 128>>>(x, gamma, beta);
    gemm_mma<DDIM, DDIM, FDIM, 1><<<dim3(FDIM / 128, MAX_MT, 1), CTA_THREADS, SMEM_GEMM>>>(
        (const float*)pxn, W1, b1, (float*)pH);
    gemm_mma<FDIM / KSPLIT, FDIM, DDIM, 2><<<dim3(DDIM / 128, MAX_MT, KSPLIT), CTA_THREADS, SMEM_GEMM>>>(
        (const float*)pH, W2, nullptr, (float*)ppart);
    combine_kernel<<<TOKS, 128>>>(x, b2, out);
}